// round 2
// baseline (speedup 1.0000x reference)
#include <cuda_runtime.h>

#define HEADS 8
#define NSEQ  4096
#define FIN   512
#define HD    64
#define FOUT  512
#define NEG_INF -1e30f

// Scratch (allocation-free rule: __device__ globals)
__device__ float g_q[HEADS * NSEQ * HD];
__device__ float g_k[HEADS * NSEQ * HD];
__device__ float g_v[HEADS * NSEQ * HD];
__device__ float g_hcat[NSEQ * HEADS * HD];

// ---------------------------------------------------------------------------
// Kernel 1: QKV projection. One block = one (head, 64-row) tile, computes
// Q, K, V simultaneously (X tile loaded once into smem).
// C[n][d] = sum_f X[n][f] * W[d][f]   (both K-major)
// ---------------------------------------------------------------------------
__global__ void __launch_bounds__(256) qkv_kernel(
    const float* __restrict__ X,
    const float* __restrict__ WQ,
    const float* __restrict__ WK,
    const float* __restrict__ WV)
{
    __shared__ float As[64][33];        // X tile   [n][f]
    __shared__ float Bs[3][64][33];     // W tiles  [d][f]

    const int head = blockIdx.z;
    const int m0   = blockIdx.x * 64;
    const int tid  = threadIdx.x;
    const int ty   = tid >> 4;          // 0..15
    const int tx   = tid & 15;          // 0..15

    const float* A  = X  + (size_t)head * NSEQ * FIN;
    const float* Bq = WQ + (size_t)head * HD * FIN;
    const float* Bk = WK + (size_t)head * HD * FIN;
    const float* Bv = WV + (size_t)head * HD * FIN;

    float acc[3][4][4];
    #pragma unroll
    for (int w = 0; w < 3; w++)
        #pragma unroll
        for (int i = 0; i < 4; i++)
            #pragma unroll
            for (int j = 0; j < 4; j++)
                acc[w][i][j] = 0.0f;

    const int lk = tid & 31;            // f within chunk
    const int lm = tid >> 5;            // row base (8 rows/iter)

    for (int k0 = 0; k0 < FIN; k0 += 32) {
        #pragma unroll
        for (int r = 0; r < 64; r += 8) {
            As[lm + r][lk]    = A [(size_t)(m0 + lm + r) * FIN + k0 + lk];
            Bs[0][lm + r][lk] = Bq[(size_t)(lm + r) * FIN + k0 + lk];
            Bs[1][lm + r][lk] = Bk[(size_t)(lm + r) * FIN + k0 + lk];
            Bs[2][lm + r][lk] = Bv[(size_t)(lm + r) * FIN + k0 + lk];
        }
        __syncthreads();

        #pragma unroll 8
        for (int k = 0; k < 32; k++) {
            float a[4];
            #pragma unroll
            for (int i = 0; i < 4; i++) a[i] = As[ty * 4 + i][k];
            #pragma unroll
            for (int w = 0; w < 3; w++) {
                float b[4];
                #pragma unroll
                for (int j = 0; j < 4; j++) b[j] = Bs[w][tx * 4 + j][k];
                #pragma unroll
                for (int i = 0; i < 4; i++)
                    #pragma unroll
                    for (int j = 0; j < 4; j++)
                        acc[w][i][j] = fmaf(a[i], b[j], acc[w][i][j]);
            }
        }
        __syncthreads();
    }

    float* outq = g_q + (size_t)head * NSEQ * HD;
    float* outk = g_k + (size_t)head * NSEQ * HD;
    float* outv = g_v + (size_t)head * NSEQ * HD;
    #pragma unroll
    for (int i = 0; i < 4; i++) {
        const size_t row = (size_t)(m0 + ty * 4 + i) * HD + tx * 4;
        float4 q4 = make_float4(acc[0][i][0], acc[0][i][1], acc[0][i][2], acc[0][i][3]);
        float4 k4 = make_float4(acc[1][i][0], acc[1][i][1], acc[1][i][2], acc[1][i][3]);
        float4 v4 = make_float4(acc[2][i][0], acc[2][i][1], acc[2][i][2], acc[2][i][3]);
        *(float4*)(outq + row) = q4;
        *(float4*)(outk + row) = k4;
        *(float4*)(outv + row) = v4;
    }
}

// ---------------------------------------------------------------------------
// Kernel 2: flash-attention. One block = one (head, 64-query) tile.
// Loops over 64 key tiles: S = Q K^T / 8 (masked) -> online softmax -> O += P V.
// Dynamic smem: Qs, Ks, Vs, Ss (64x65 each) + m/l/alpha (64 each).
// ---------------------------------------------------------------------------
#define PITCH 65
__global__ void __launch_bounds__(256) attn_kernel(const int* __restrict__ mask)
{
    extern __shared__ float sm[];
    float (*Qs)[PITCH] = (float(*)[PITCH])sm;
    float (*Ks)[PITCH] = Qs + 64;
    float (*Vs)[PITCH] = Ks + 64;
    float (*Ss)[PITCH] = Vs + 64;
    float* m_s     = (float*)(Ss + 64);
    float* l_s     = m_s + 64;
    float* alpha_s = l_s + 64;

    const int head = blockIdx.y;
    const int q0   = blockIdx.x * 64;
    const int tid  = threadIdx.x;
    const int ty   = tid >> 4;
    const int tx   = tid & 15;
    const int warp = tid >> 5;
    const int lane = tid & 31;

    const float* Q = g_q + (size_t)head * NSEQ * HD;
    const float* K = g_k + (size_t)head * NSEQ * HD;
    const float* V = g_v + (size_t)head * NSEQ * HD;
    const int*   M = mask + (size_t)head * NSEQ * NSEQ;

    // Load Q tile (64x64): each thread 4 float4s
    {
        const int r  = tid >> 4;          // 0..15
        const int c4 = tid & 15;          // float4 column
        #pragma unroll
        for (int rr = 0; rr < 64; rr += 16) {
            float4 v4 = *(const float4*)(Q + (size_t)(q0 + r + rr) * HD + c4 * 4);
            Qs[r + rr][c4 * 4 + 0] = v4.x;
            Qs[r + rr][c4 * 4 + 1] = v4.y;
            Qs[r + rr][c4 * 4 + 2] = v4.z;
            Qs[r + rr][c4 * 4 + 3] = v4.w;
        }
    }
    if (tid < 64) { m_s[tid] = -3e38f; l_s[tid] = 0.0f; }

    float o[4][4];
    #pragma unroll
    for (int i = 0; i < 4; i++)
        #pragma unroll
        for (int j = 0; j < 4; j++) o[i][j] = 0.0f;

    for (int kt = 0; kt < NSEQ / 64; kt++) {
        const int k0 = kt * 64;
        __syncthreads();   // previous iteration's consumers done

        // Load K & V tiles
        {
            const int r  = tid >> 4;
            const int c4 = tid & 15;
            #pragma unroll
            for (int rr = 0; rr < 64; rr += 16) {
                float4 kv = *(const float4*)(K + (size_t)(k0 + r + rr) * HD + c4 * 4);
                float4 vv = *(const float4*)(V + (size_t)(k0 + r + rr) * HD + c4 * 4);
                Ks[r + rr][c4 * 4 + 0] = kv.x; Ks[r + rr][c4 * 4 + 1] = kv.y;
                Ks[r + rr][c4 * 4 + 2] = kv.z; Ks[r + rr][c4 * 4 + 3] = kv.w;
                Vs[r + rr][c4 * 4 + 0] = vv.x; Vs[r + rr][c4 * 4 + 1] = vv.y;
                Vs[r + rr][c4 * 4 + 2] = vv.z; Vs[r + rr][c4 * 4 + 3] = vv.w;
            }
        }
        // Prefetch mask for this thread's 4x4 S micro-tile (hides under GEMM)
        int4 mk[4];
        #pragma unroll
        for (int i = 0; i < 4; i++)
            mk[i] = *(const int4*)(M + (size_t)(q0 + ty * 4 + i) * NSEQ + k0 + tx * 4);

        __syncthreads();   // tiles ready

        // S = Q K^T
        float s[4][4];
        #pragma unroll
        for (int i = 0; i < 4; i++)
            #pragma unroll
            for (int j = 0; j < 4; j++) s[i][j] = 0.0f;
        #pragma unroll 8
        for (int d = 0; d < 64; d++) {
            float a[4], b[4];
            #pragma unroll
            for (int i = 0; i < 4; i++) a[i] = Qs[ty * 4 + i][d];
            #pragma unroll
            for (int j = 0; j < 4; j++) b[j] = Ks[tx * 4 + j][d];
            #pragma unroll
            for (int i = 0; i < 4; i++)
                #pragma unroll
                for (int j = 0; j < 4; j++)
                    s[i][j] = fmaf(a[i], b[j], s[i][j]);
        }
        // scale + mask -> Ss
        #pragma unroll
        for (int i = 0; i < 4; i++) {
            const int* mp = (const int*)&mk[i];
            #pragma unroll
            for (int j = 0; j < 4; j++)
                Ss[ty * 4 + i][tx * 4 + j] = mp[j] ? s[i][j] * 0.125f : NEG_INF;
        }
        __syncthreads();

        // Online softmax: warp w owns rows w*8 .. w*8+7
        #pragma unroll
        for (int rr = 0; rr < 8; rr++) {
            const int r = warp * 8 + rr;
            float v0 = Ss[r][lane], v1 = Ss[r][lane + 32];
            float mx = fmaxf(v0, v1);
            #pragma unroll
            for (int off = 16; off > 0; off >>= 1)
                mx = fmaxf(mx, __shfl_xor_sync(0xFFFFFFFFu, mx, off));
            const float m_old = m_s[r];
            const float m_new = fmaxf(m_old, mx);
            const float p0 = __expf(v0 - m_new);
            const float p1 = __expf(v1 - m_new);
            Ss[r][lane] = p0; Ss[r][lane + 32] = p1;
            float ssum = p0 + p1;
            #pragma unroll
            for (int off = 16; off > 0; off >>= 1)
                ssum += __shfl_xor_sync(0xFFFFFFFFu, ssum, off);
            if (lane == 0) {
                const float al = __expf(m_old - m_new);
                alpha_s[r] = al;
                l_s[r] = l_s[r] * al + ssum;
                m_s[r] = m_new;
            }
        }
        __syncthreads();

        // O = O*alpha + P V
        float al[4];
        #pragma unroll
        for (int i = 0; i < 4; i++) al[i] = alpha_s[ty * 4 + i];
        #pragma unroll
        for (int i = 0; i < 4; i++)
            #pragma unroll
            for (int j = 0; j < 4; j++) o[i][j] *= al[i];
        #pragma unroll 8
        for (int d = 0; d < 64; d++) {
            float p[4], vv[4];
            #pragma unroll
            for (int i = 0; i < 4; i++) p[i] = Ss[ty * 4 + i][d];
            #pragma unroll
            for (int j = 0; j < 4; j++) vv[j] = Vs[d][tx * 4 + j];
            #pragma unroll
            for (int i = 0; i < 4; i++)
                #pragma unroll
                for (int j = 0; j < 4; j++)
                    o[i][j] = fmaf(p[i], vv[j], o[i][j]);
        }
    }
    __syncthreads();   // l_s final values visible

    // Normalize + write to concat layout: hcat[n][head*64 + d]
    #pragma unroll
    for (int i = 0; i < 4; i++) {
        const float inv = 1.0f / l_s[ty * 4 + i];
        float4 r4 = make_float4(o[i][0] * inv, o[i][1] * inv, o[i][2] * inv, o[i][3] * inv);
        *(float4*)(g_hcat + (size_t)(q0 + ty * 4 + i) * (HEADS * HD) + head * HD + tx * 4) = r4;
    }
}

// ---------------------------------------------------------------------------
// Kernel 3: output projection. out[n][o] = sum_c hcat[n][c] * WO[o][c]
// ---------------------------------------------------------------------------
__global__ void __launch_bounds__(256) proj_kernel(
    const float* __restrict__ WO, float* __restrict__ out)
{
    __shared__ float As[64][33];
    __shared__ float Bs[64][33];

    const int m0  = blockIdx.x * 64;
    const int n0  = blockIdx.y * 64;
    const int tid = threadIdx.x;
    const int ty  = tid >> 4;
    const int tx  = tid & 15;

    float acc[4][4];
    #pragma unroll
    for (int i = 0; i < 4; i++)
        #pragma unroll
        for (int j = 0; j < 4; j++) acc[i][j] = 0.0f;

    const int lk = tid & 31;
    const int lm = tid >> 5;

    for (int k0 = 0; k0 < HEADS * HD; k0 += 32) {
        #pragma unroll
        for (int r = 0; r < 64; r += 8) {
            As[lm + r][lk] = g_hcat[(size_t)(m0 + lm + r) * (HEADS * HD) + k0 + lk];
            Bs[lm + r][lk] = WO[(size_t)(n0 + lm + r) * (HEADS * HD) + k0 + lk];
        }
        __syncthreads();
        #pragma unroll 8
        for (int k = 0; k < 32; k++) {
            float a[4], b[4];
            #pragma unroll
            for (int i = 0; i < 4; i++) a[i] = As[ty * 4 + i][k];
            #pragma unroll
            for (int j = 0; j < 4; j++) b[j] = Bs[tx * 4 + j][k];
            #pragma unroll
            for (int i = 0; i < 4; i++)
                #pragma unroll
                for (int j = 0; j < 4; j++)
                    acc[i][j] = fmaf(a[i], b[j], acc[i][j]);
        }
        __syncthreads();
    }

    #pragma unroll
    for (int i = 0; i < 4; i++) {
        float4 r4 = make_float4(acc[i][0], acc[i][1], acc[i][2], acc[i][3]);
        *(float4*)(out + (size_t)(m0 + ty * 4 + i) * FOUT + n0 + tx * 4) = r4;
    }
}

// ---------------------------------------------------------------------------
extern "C" void kernel_launch(void* const* d_in, const int* in_sizes, int n_in,
                              void* d_out, int out_size)
{
    const float* X    = (const float*)d_in[0];
    const int*   mask = (const int*)  d_in[1];
    const float* WQ   = (const float*)d_in[2];
    const float* WK   = (const float*)d_in[3];
    const float* WV   = (const float*)d_in[4];
    const float* WO   = (const float*)d_in[5];
    float* out = (float*)d_out;

    qkv_kernel<<<dim3(NSEQ / 64, 1, HEADS), 256>>>(X, WQ, WK, WV);

    const size_t smem = (4 * 64 * PITCH + 3 * 64) * sizeof(float);
    cudaFuncSetAttribute(attn_kernel, cudaFuncAttributeMaxDynamicSharedMemorySize, (int)smem);
    attn_kernel<<<dim3(NSEQ / 64, HEADS), 256, smem>>>(mask);

    proj_kernel<<<dim3(NSEQ / 64, FOUT / 64), 256>>>(WO, out);
}

// round 5
// speedup vs baseline: 2.0815x; 2.0815x over previous
#include <cuda_runtime.h>
#include <cstdint>

#define HEADS 8
#define NSEQ  4096
#define FIN   512
#define HD    64
#define FOUT  512
#define NEG_INF -1e30f

// Scratch (allocation-free rule: __device__ globals)
__device__ float g_q[HEADS * NSEQ * HD];
__device__ float g_k[HEADS * NSEQ * HD];
__device__ float g_v[HEADS * NSEQ * HD];
__device__ float g_hcat[NSEQ * HEADS * HD];

__device__ __forceinline__ uint32_t f2tf(float f) {
    uint32_t r;
    asm("cvt.rna.tf32.f32 %0, %1;" : "=r"(r) : "f"(f));
    return r;
}

__device__ __forceinline__ void mma_tf32(float c[4],
    uint32_t a0, uint32_t a1, uint32_t a2, uint32_t a3,
    uint32_t b0, uint32_t b1)
{
    asm volatile(
        "mma.sync.aligned.m16n8k8.row.col.f32.tf32.tf32.f32 "
        "{%0,%1,%2,%3}, {%4,%5,%6,%7}, {%8,%9}, {%0,%1,%2,%3};"
        : "+f"(c[0]), "+f"(c[1]), "+f"(c[2]), "+f"(c[3])
        : "r"(a0), "r"(a1), "r"(a2), "r"(a3), "r"(b0), "r"(b1));
}

// ---------------------------------------------------------------------------
// Kernel 1: QKV projection (fp32 FFMA).
// ---------------------------------------------------------------------------
__global__ void __launch_bounds__(256) qkv_kernel(
    const float* __restrict__ X,
    const float* __restrict__ WQ,
    const float* __restrict__ WK,
    const float* __restrict__ WV)
{
    __shared__ float As[64][33];
    __shared__ float Bs[3][64][33];

    const int head = blockIdx.z;
    const int m0   = blockIdx.x * 64;
    const int tid  = threadIdx.x;
    const int ty   = tid >> 4;
    const int tx   = tid & 15;

    const float* A  = X  + (size_t)head * NSEQ * FIN;
    const float* Bq = WQ + (size_t)head * HD * FIN;
    const float* Bk = WK + (size_t)head * HD * FIN;
    const float* Bv = WV + (size_t)head * HD * FIN;

    float acc[3][4][4];
    #pragma unroll
    for (int w = 0; w < 3; w++)
        #pragma unroll
        for (int i = 0; i < 4; i++)
            #pragma unroll
            for (int j = 0; j < 4; j++)
                acc[w][i][j] = 0.0f;

    const int lk = tid & 31;
    const int lm = tid >> 5;

    for (int k0 = 0; k0 < FIN; k0 += 32) {
        #pragma unroll
        for (int r = 0; r < 64; r += 8) {
            As[lm + r][lk]    = A [(size_t)(m0 + lm + r) * FIN + k0 + lk];
            Bs[0][lm + r][lk] = Bq[(size_t)(lm + r) * FIN + k0 + lk];
            Bs[1][lm + r][lk] = Bk[(size_t)(lm + r) * FIN + k0 + lk];
            Bs[2][lm + r][lk] = Bv[(size_t)(lm + r) * FIN + k0 + lk];
        }
        __syncthreads();

        #pragma unroll 8
        for (int k = 0; k < 32; k++) {
            float a[4];
            #pragma unroll
            for (int i = 0; i < 4; i++) a[i] = As[ty * 4 + i][k];
            #pragma unroll
            for (int w = 0; w < 3; w++) {
                float b[4];
                #pragma unroll
                for (int j = 0; j < 4; j++) b[j] = Bs[w][tx * 4 + j][k];
                #pragma unroll
                for (int i = 0; i < 4; i++)
                    #pragma unroll
                    for (int j = 0; j < 4; j++)
                        acc[w][i][j] = fmaf(a[i], b[j], acc[w][i][j]);
            }
        }
        __syncthreads();
    }

    float* outq = g_q + (size_t)head * NSEQ * HD;
    float* outk = g_k + (size_t)head * NSEQ * HD;
    float* outv = g_v + (size_t)head * NSEQ * HD;
    #pragma unroll
    for (int i = 0; i < 4; i++) {
        const size_t row = (size_t)(m0 + ty * 4 + i) * HD + tx * 4;
        *(float4*)(outq + row) = make_float4(acc[0][i][0], acc[0][i][1], acc[0][i][2], acc[0][i][3]);
        *(float4*)(outk + row) = make_float4(acc[1][i][0], acc[1][i][1], acc[1][i][2], acc[1][i][3]);
        *(float4*)(outv + row) = make_float4(acc[2][i][0], acc[2][i][1], acc[2][i][2], acc[2][i][3]);
    }
}

// ---------------------------------------------------------------------------
// Kernel 2: flash-attention, TF32 tensor cores (mma.sync m16n8k8).
// Block = (head, 64-query tile), 8 warps. Warp (wm,wn) owns rows wm*16..+16,
// cols wn*32..+32 of the 64x64 S tile and of the 64-dim O tile.
// Smem pitches: Q/K/P = 68 (==4 mod 32), V = 72 (==8 mod 32) -> all fragment
// LDS patterns are bank-bijective (conflict-free).
// ---------------------------------------------------------------------------
#define QP 68
#define VP 72

__global__ void __launch_bounds__(256) attn_kernel(const int* __restrict__ mask)
{
    extern __shared__ uint32_t sm[];
    uint32_t* Qs = sm;                       // 64*QP
    uint32_t* Ks = Qs + 64 * QP;             // 64*QP
    uint32_t* Ps = Ks + 64 * QP;             // 64*QP
    uint32_t* Vs = Ps + 64 * QP;             // 64*VP
    float* pmax = (float*)(Vs + 64 * VP);    // [2][64]
    float* psum = pmax + 128;                // [2][64]
    float* m_s  = psum + 128;                // [64]
    float* l_s  = m_s + 64;                  // [64]

    const int head = blockIdx.y;
    const int q0   = blockIdx.x * 64;
    const int tid  = threadIdx.x;
    const int warp = tid >> 5;
    const int lane = tid & 31;
    const int wm   = warp >> 1;              // 0..3
    const int wn   = warp & 1;               // 0..1
    const int gr   = lane >> 2;              // 0..7
    const int gc   = lane & 3;               // 0..3

    const float* Q = g_q + (size_t)head * NSEQ * HD;
    const float* K = g_k + (size_t)head * NSEQ * HD;
    const float* V = g_v + (size_t)head * NSEQ * HD;
    const int*   M = mask + (size_t)head * NSEQ * NSEQ;

    // Load Q tile -> tf32 smem
    {
        const int r = tid >> 4, c4 = (tid & 15) * 4;
        #pragma unroll
        for (int rr = 0; rr < 64; rr += 16) {
            float4 v = *(const float4*)(Q + (size_t)(q0 + r + rr) * HD + c4);
            Qs[(r + rr) * QP + c4 + 0] = f2tf(v.x);
            Qs[(r + rr) * QP + c4 + 1] = f2tf(v.y);
            Qs[(r + rr) * QP + c4 + 2] = f2tf(v.z);
            Qs[(r + rr) * QP + c4 + 3] = f2tf(v.w);
        }
    }
    if (tid < 64) { m_s[tid] = -3e38f; l_s[tid] = 0.0f; }

    float o[4][4];
    #pragma unroll
    for (int c = 0; c < 4; c++)
        #pragma unroll
        for (int j = 0; j < 4; j++) o[c][j] = 0.0f;

    const int r0 = wm * 16 + gr;   // local q row (frag rows r0, r0+8)
    const int r1 = r0 + 8;

    for (int kt = 0; kt < NSEQ / 64; kt++) {
        const int k0 = kt * 64;
        __syncthreads();  // sync1: previous iteration fully consumed

        // Load K & V tiles -> tf32 smem
        {
            const int r = tid >> 4, c4 = (tid & 15) * 4;
            #pragma unroll
            for (int rr = 0; rr < 64; rr += 16) {
                float4 kv = *(const float4*)(K + (size_t)(k0 + r + rr) * HD + c4);
                float4 vv = *(const float4*)(V + (size_t)(k0 + r + rr) * HD + c4);
                Ks[(r + rr) * QP + c4 + 0] = f2tf(kv.x);
                Ks[(r + rr) * QP + c4 + 1] = f2tf(kv.y);
                Ks[(r + rr) * QP + c4 + 2] = f2tf(kv.z);
                Ks[(r + rr) * QP + c4 + 3] = f2tf(kv.w);
                Vs[(r + rr) * VP + c4 + 0] = f2tf(vv.x);
                Vs[(r + rr) * VP + c4 + 1] = f2tf(vv.y);
                Vs[(r + rr) * VP + c4 + 2] = f2tf(vv.z);
                Vs[(r + rr) * VP + c4 + 3] = f2tf(vv.w);
            }
        }
        // Prefetch mask fragments (coords == C-fragment coords); hides under MMA
        int2 mk[4][2];
        #pragma unroll
        for (int c = 0; c < 4; c++) {
            const int col = k0 + wn * 32 + c * 8 + gc * 2;
            mk[c][0] = *(const int2*)(M + (size_t)(q0 + r0) * NSEQ + col);
            mk[c][1] = *(const int2*)(M + (size_t)(q0 + r1) * NSEQ + col);
        }
        __syncthreads();  // sync2: tiles ready

        // ---- S = Q K^T (tf32 MMA) ----
        float sc[4][4];
        #pragma unroll
        for (int c = 0; c < 4; c++)
            #pragma unroll
            for (int j = 0; j < 4; j++) sc[c][j] = 0.0f;

        #pragma unroll
        for (int kk = 0; kk < 64; kk += 8) {
            const uint32_t a0 = Qs[r0 * QP + kk + gc];
            const uint32_t a1 = Qs[r1 * QP + kk + gc];
            const uint32_t a2 = Qs[r0 * QP + kk + gc + 4];
            const uint32_t a3 = Qs[r1 * QP + kk + gc + 4];
            #pragma unroll
            for (int c = 0; c < 4; c++) {
                const int key = wn * 32 + c * 8 + gr;
                const uint32_t b0 = Ks[key * QP + kk + gc];
                const uint32_t b1 = Ks[key * QP + kk + gc + 4];
                mma_tf32(sc[c], a0, a1, a2, a3, b0, b1);
            }
        }

        // ---- scale + mask ----
        #pragma unroll
        for (int c = 0; c < 4; c++) {
            sc[c][0] = mk[c][0].x ? sc[c][0] * 0.125f : NEG_INF;
            sc[c][1] = mk[c][0].y ? sc[c][1] * 0.125f : NEG_INF;
            sc[c][2] = mk[c][1].x ? sc[c][2] * 0.125f : NEG_INF;
            sc[c][3] = mk[c][1].y ? sc[c][3] * 0.125f : NEG_INF;
        }

        // ---- partial row max (per-warp, 32 cols) ----
        float rm0 = -3e38f, rm1 = -3e38f;
        #pragma unroll
        for (int c = 0; c < 4; c++) {
            rm0 = fmaxf(rm0, fmaxf(sc[c][0], sc[c][1]));
            rm1 = fmaxf(rm1, fmaxf(sc[c][2], sc[c][3]));
        }
        rm0 = fmaxf(rm0, __shfl_xor_sync(0xFFFFFFFFu, rm0, 1));
        rm0 = fmaxf(rm0, __shfl_xor_sync(0xFFFFFFFFu, rm0, 2));
        rm1 = fmaxf(rm1, __shfl_xor_sync(0xFFFFFFFFu, rm1, 1));
        rm1 = fmaxf(rm1, __shfl_xor_sync(0xFFFFFFFFu, rm1, 2));
        if (gc == 0) { pmax[wn * 64 + r0] = rm0; pmax[wn * 64 + r1] = rm1; }
        __syncthreads();  // sync3: pmax visible

        const float mo0 = m_s[r0], mo1 = m_s[r1];
        const float mn0 = fmaxf(mo0, fmaxf(pmax[r0], pmax[64 + r0]));
        const float mn1 = fmaxf(mo1, fmaxf(pmax[r1], pmax[64 + r1]));

        // ---- exp, partial sums, P -> smem (tf32) ----
        float rs0 = 0.0f, rs1 = 0.0f;
        #pragma unroll
        for (int c = 0; c < 4; c++) {
            sc[c][0] = __expf(sc[c][0] - mn0);
            sc[c][1] = __expf(sc[c][1] - mn0);
            sc[c][2] = __expf(sc[c][2] - mn1);
            sc[c][3] = __expf(sc[c][3] - mn1);
            rs0 += sc[c][0] + sc[c][1];
            rs1 += sc[c][2] + sc[c][3];
            const int col = wn * 32 + c * 8 + gc * 2;
            Ps[r0 * QP + col]     = f2tf(sc[c][0]);
            Ps[r0 * QP + col + 1] = f2tf(sc[c][1]);
            Ps[r1 * QP + col]     = f2tf(sc[c][2]);
            Ps[r1 * QP + col + 1] = f2tf(sc[c][3]);
        }
        rs0 += __shfl_xor_sync(0xFFFFFFFFu, rs0, 1);
        rs0 += __shfl_xor_sync(0xFFFFFFFFu, rs0, 2);
        rs1 += __shfl_xor_sync(0xFFFFFFFFu, rs1, 1);
        rs1 += __shfl_xor_sync(0xFFFFFFFFu, rs1, 2);
        if (gc == 0) { psum[wn * 64 + r0] = rs0; psum[wn * 64 + r1] = rs1; }

        const float al0 = __expf(mo0 - mn0);
        const float al1 = __expf(mo1 - mn1);
        __syncthreads();  // sync4: Ps + psum visible

        // ---- O rescale + O += P V (tf32 MMA) ----
        #pragma unroll
        for (int c = 0; c < 4; c++) {
            o[c][0] *= al0; o[c][1] *= al0;
            o[c][2] *= al1; o[c][3] *= al1;
        }
        #pragma unroll
        for (int kk = 0; kk < 64; kk += 8) {
            const uint32_t a0 = Ps[r0 * QP + kk + gc];
            const uint32_t a1 = Ps[r1 * QP + kk + gc];
            const uint32_t a2 = Ps[r0 * QP + kk + gc + 4];
            const uint32_t a3 = Ps[r1 * QP + kk + gc + 4];
            #pragma unroll
            for (int c = 0; c < 4; c++) {
                const int d = wn * 32 + c * 8 + gr;
                const uint32_t b0 = Vs[(kk + gc) * VP + d];
                const uint32_t b1 = Vs[(kk + gc + 4) * VP + d];
                mma_tf32(o[c], a0, a1, a2, a3, b0, b1);
            }
        }

        // ---- m/l update (one warp per row group) ----
        if (wn == 0 && lane < 16) {
            const int r = wm * 16 + lane;
            const float mo = m_s[r];
            const float mn = fmaxf(mo, fmaxf(pmax[r], pmax[64 + r]));
            l_s[r] = l_s[r] * __expf(mo - mn) + psum[r] + psum[64 + r];
            m_s[r] = mn;
        }
    }
    __syncthreads();

    const float inv0 = 1.0f / l_s[r0];
    const float inv1 = 1.0f / l_s[r1];
    #pragma unroll
    for (int c = 0; c < 4; c++) {
        const int d = head * HD + wn * 32 + c * 8 + gc * 2;
        *(float2*)(g_hcat + (size_t)(q0 + r0) * (HEADS * HD) + d) =
            make_float2(o[c][0] * inv0, o[c][1] * inv0);
        *(float2*)(g_hcat + (size_t)(q0 + r1) * (HEADS * HD) + d) =
            make_float2(o[c][2] * inv1, o[c][3] * inv1);
    }
}

// ---------------------------------------------------------------------------
// Kernel 3: output projection (fp32 FFMA).
// ---------------------------------------------------------------------------
__global__ void __launch_bounds__(256) proj_kernel(
    const float* __restrict__ WO, float* __restrict__ out)
{
    __shared__ float As[64][33];
    __shared__ float Bs[64][33];

    const int m0  = blockIdx.x * 64;
    const int n0  = blockIdx.y * 64;
    const int tid = threadIdx.x;
    const int ty  = tid >> 4;
    const int tx  = tid & 15;

    float acc[4][4];
    #pragma unroll
    for (int i = 0; i < 4; i++)
        #pragma unroll
        for (int j = 0; j < 4; j++) acc[i][j] = 0.0f;

    const int lk = tid & 31;
    const int lm = tid >> 5;

    for (int k0 = 0; k0 < HEADS * HD; k0 += 32) {
        #pragma unroll
        for (int r = 0; r < 64; r += 8) {
            As[lm + r][lk] = g_hcat[(size_t)(m0 + lm + r) * (HEADS * HD) + k0 + lk];
            Bs[lm + r][lk] = WO[(size_t)(n0 + lm + r) * (HEADS * HD) + k0 + lk];
        }
        __syncthreads();
        #pragma unroll 8
        for (int k = 0; k < 32; k++) {
            float a[4], b[4];
            #pragma unroll
            for (int i = 0; i < 4; i++) a[i] = As[ty * 4 + i][k];
            #pragma unroll
            for (int j = 0; j < 4; j++) b[j] = Bs[tx * 4 + j][k];
            #pragma unroll
            for (int i = 0; i < 4; i++)
                #pragma unroll
                for (int j = 0; j < 4; j++)
                    acc[i][j] = fmaf(a[i], b[j], acc[i][j]);
        }
        __syncthreads();
    }

    #pragma unroll
    for (int i = 0; i < 4; i++) {
        *(float4*)(out + (size_t)(m0 + ty * 4 + i) * FOUT + n0 + tx * 4) =
            make_float4(acc[i][0], acc[i][1], acc[i][2], acc[i][3]);
    }
}

// ---------------------------------------------------------------------------
extern "C" void kernel_launch(void* const* d_in, const int* in_sizes, int n_in,
                              void* d_out, int out_size)
{
    const float* X    = (const float*)d_in[0];
    const int*   mask = (const int*)  d_in[1];
    const float* WQ   = (const float*)d_in[2];
    const float* WK   = (const float*)d_in[3];
    const float* WV   = (const float*)d_in[4];
    const float* WO   = (const float*)d_in[5];
    float* out = (float*)d_out;

    qkv_kernel<<<dim3(NSEQ / 64, 1, HEADS), 256>>>(X, WQ, WK, WV);

    const size_t smem = (size_t)(3 * 64 * QP + 64 * VP) * 4 + 384 * 4;
    cudaFuncSetAttribute(attn_kernel, cudaFuncAttributeMaxDynamicSharedMemorySize, (int)smem);
    attn_kernel<<<dim3(NSEQ / 64, HEADS), 256, smem>>>(mask);

    proj_kernel<<<dim3(NSEQ / 64, FOUT / 64), 256>>>(WO, out);
}